// round 7
// baseline (speedup 1.0000x reference)
#include <cuda_runtime.h>
#include <cuda_fp16.h>
#include <math.h>
#include <stdint.h>

// ---------------- problem constants ----------------
#define LAYERS 12
#define HEADS  12
#define CDIM   768
#define TSEQ   1024
#define BATCH  4
#define MROWS  (BATCH*TSEQ)      // 4096
#define C3     (3*CDIM)          // 2304
#define C4     (4*CDIM)          // 3072
#define DHEAD  64

// ---------------- scratch (device globals: no allocation allowed) ----------
__device__ float  g_x  [MROWS*CDIM];          // fp32 residual stream
__device__ __half g_qkv[MROWS*C3];            // fp16 qkv
__device__ __half g_h  [MROWS*CDIM];          // fp16 LN output (GEMM A)
__device__ __half g_y  [MROWS*CDIM];          // fp16 attention output
__device__ __half g_fc [MROWS*C4];            // fp16 gelu output
// transposed (to [N,K] K-major) fp16 weights
__device__ __half g_wqkvT[LAYERS*C3*CDIM];
__device__ __half g_waoT [LAYERS*CDIM*CDIM];
__device__ __half g_wfcT [LAYERS*C4*CDIM];
__device__ __half g_wfpT [LAYERS*CDIM*C4];

// ---------------- helpers ----------------
__device__ __forceinline__ uint32_t smem_u32(const void* p) {
    uint32_t a;
    asm("{ .reg .u64 t; cvta.to.shared.u64 t, %1; cvt.u32.u64 %0, t; }"
        : "=r"(a) : "l"(p));
    return a;
}
__device__ __forceinline__ void cpa16(uint32_t saddr, const void* g) {
    asm volatile("cp.async.cg.shared.global [%0], [%1], 16;" :: "r"(saddr), "l"(g));
}
#define CP_COMMIT()  asm volatile("cp.async.commit_group;" ::: "memory")
#define CP_WAIT(n)   asm volatile("cp.async.wait_group %0;" :: "n"(n) : "memory")

#define LDMATRIX_X4(r0, r1, r2, r3, addr) \
    asm volatile("ldmatrix.sync.aligned.m8n8.x4.shared.b16 {%0,%1,%2,%3}, [%4];" \
        : "=r"(r0), "=r"(r1), "=r"(r2), "=r"(r3) : "r"(addr))

#define LDMATRIX_X4_T(r0, r1, r2, r3, addr) \
    asm volatile("ldmatrix.sync.aligned.m8n8.x4.trans.shared.b16 {%0,%1,%2,%3}, [%4];" \
        : "=r"(r0), "=r"(r1), "=r"(r2), "=r"(r3) : "r"(addr))

#define MMA_F16(d, a0, a1, a2, a3, b0, b1) \
    asm volatile( \
        "mma.sync.aligned.m16n8k16.row.col.f32.f16.f16.f32 " \
        "{%0,%1,%2,%3},{%4,%5,%6,%7},{%8,%9},{%0,%1,%2,%3};" \
        : "+f"((d)[0]), "+f"((d)[1]), "+f"((d)[2]), "+f"((d)[3]) \
        : "r"(a0), "r"(a1), "r"(a2), "r"(a3), "r"(b0), "r"(b1))

__device__ __forceinline__ uint32_t packh2(float lo, float hi) {
    __half2 h = __floats2half2_rn(lo, hi);
    return *(uint32_t*)&h;
}

__device__ __forceinline__ float gelu_tanh(float v) {
    float c = 0.7978845608028654f * (v + 0.044715f * v * v * v);
    return 0.5f * v * (1.0f + tanhf(c));
}

// ---------------- embedding ----------------
__global__ __launch_bounds__(256) void embed_kernel(
    const int* __restrict__ idx, const float* __restrict__ wte,
    const float* __restrict__ wpe, float* __restrict__ x)
{
    int i = blockIdx.x * 256 + threadIdx.x;
    int row = i / CDIM;
    int c   = i - row * CDIM;
    int t   = row & (TSEQ - 1);
    int id  = idx[row];
    x[i] = wte[(size_t)id * CDIM + c] + wpe[(size_t)t * CDIM + c];
}

// ---------------- weight transpose (fp32 [K,N] -> fp16 [N,K]) --------------
__global__ __launch_bounds__(256) void transpose_kernel(
    const float* __restrict__ W, __half* __restrict__ WT, int K, int N)
{
    __shared__ float t[32][33];
    int l = blockIdx.z;
    const float* Wl = W + (size_t)l * K * N;
    __half* WTl = WT + (size_t)l * N * K;
    int k0 = blockIdx.y * 32, n0 = blockIdx.x * 32;
    int tx = threadIdx.x & 31, ty = threadIdx.x >> 5;   // 32 x 8
    #pragma unroll
    for (int r = ty; r < 32; r += 8)
        t[r][tx] = Wl[(size_t)(k0 + r) * N + n0 + tx];
    __syncthreads();
    #pragma unroll
    for (int r = ty; r < 32; r += 8)
        WTl[(size_t)(n0 + r) * K + k0 + tx] = __float2half_rn(t[tx][r]);
}

// ---------------- layernorm (fp16 output) ----------------
__global__ __launch_bounds__(256) void ln_kernel(
    const float* __restrict__ x, const float* __restrict__ w,
    const float* __restrict__ b, __half* __restrict__ out)
{
    int row = blockIdx.x;
    const float* xr = x + (size_t)row * CDIM;
    float s = 0.f, s2 = 0.f;
    for (int i = threadIdx.x; i < CDIM; i += 256) {
        float v = xr[i]; s += v; s2 += v * v;
    }
    #pragma unroll
    for (int o = 16; o; o >>= 1) {
        s  += __shfl_xor_sync(0xffffffffu, s,  o);
        s2 += __shfl_xor_sync(0xffffffffu, s2, o);
    }
    __shared__ float rbuf[16];
    int wid = threadIdx.x >> 5, lane = threadIdx.x & 31;
    if (lane == 0) { rbuf[wid] = s; rbuf[8 + wid] = s2; }
    __syncthreads();
    float ts = 0.f, ts2 = 0.f;
    #pragma unroll
    for (int i = 0; i < 8; i++) { ts += rbuf[i]; ts2 += rbuf[8 + i]; }
    float mu  = ts * (1.0f / CDIM);
    float var = ts2 * (1.0f / CDIM) - mu * mu;
    float rs  = rsqrtf(var + 1e-5f);
    __half* orow = out + (size_t)row * CDIM;
    for (int i = threadIdx.x; i < CDIM; i += 256) {
        orow[i] = __float2half_rn((xr[i] - mu) * rs * w[i] + b[i]);
    }
}

// ---------------- final LN + head matvec ----------------
__global__ __launch_bounds__(256) void head_kernel(
    const float* __restrict__ x, const float* __restrict__ lw,
    const float* __restrict__ lb, const float* __restrict__ wh,
    float* __restrict__ out)
{
    int row = blockIdx.x;
    const float* xr = x + (size_t)row * CDIM;
    float s = 0.f, s2 = 0.f;
    for (int i = threadIdx.x; i < CDIM; i += 256) {
        float v = xr[i]; s += v; s2 += v * v;
    }
    #pragma unroll
    for (int o = 16; o; o >>= 1) {
        s  += __shfl_xor_sync(0xffffffffu, s,  o);
        s2 += __shfl_xor_sync(0xffffffffu, s2, o);
    }
    __shared__ float rbuf[16];
    int wid = threadIdx.x >> 5, lane = threadIdx.x & 31;
    if (lane == 0) { rbuf[wid] = s; rbuf[8 + wid] = s2; }
    __syncthreads();
    float ts = 0.f, ts2 = 0.f;
    #pragma unroll
    for (int i = 0; i < 8; i++) { ts += rbuf[i]; ts2 += rbuf[8 + i]; }
    float mu  = ts * (1.0f / CDIM);
    float var = ts2 * (1.0f / CDIM) - mu * mu;
    float rs  = rsqrtf(var + 1e-5f);

    float acc = 0.f;
    for (int i = threadIdx.x; i < CDIM; i += 256) {
        float hn = (xr[i] - mu) * rs * lw[i] + lb[i];
        acc += hn * wh[i];
    }
    #pragma unroll
    for (int o = 16; o; o >>= 1) acc += __shfl_xor_sync(0xffffffffu, acc, o);
    __syncthreads();
    if (lane == 0) rbuf[wid] = acc;
    __syncthreads();
    if (threadIdx.x == 0) {
        float t = 0.f;
        #pragma unroll
        for (int i = 0; i < 8; i++) t += rbuf[i];
        out[row] = t;
    }
}

// ======================= fp16 tensor-core GEMM 128x128 =======================
#define NSTAGE 4
#define STAGE_BYTES 16384
#define HG_SMEM (NSTAGE*STAGE_BYTES)

template <int EPI>  // 0=+bias->f32  1=+bias+res->f32  2=+bias,gelu->f16  3=+bias->f16
__global__ __launch_bounds__(128, 2) void hgemm(
    const __half* __restrict__ A, const __half* __restrict__ BT,
    const float* __restrict__ bias, const float* __restrict__ R,
    void* __restrict__ Cv, int M, int N, int K)
{
    extern __shared__ __align__(128) char smem[];
    uint32_t sbase = smem_u32(smem);
    int tid = threadIdx.x, lane = tid & 31, wid = tid >> 5;
    int wm = wid >> 1, wn = wid & 1;
    int bm = blockIdx.y, bn = blockIdx.x;
    const __half* Ag = A  + (size_t)bm * 128 * K;
    const __half* Bg = BT + (size_t)bn * 128 * K;
    const int nch = K >> 5;

    float acc[4][8][4];
    #pragma unroll
    for (int i = 0; i < 4; i++)
        #pragma unroll
        for (int j = 0; j < 8; j++)
            #pragma unroll
            for (int q = 0; q < 4; q++) acc[i][j][q] = 0.f;

    #define LOADC(c, s)                                                        \
    {                                                                          \
        uint32_t st_ = sbase + (s) * STAGE_BYTES;                              \
        int k0_ = (c) * 32;                                                    \
        _Pragma("unroll")                                                      \
        for (int p = 0; p < 4; p++) {                                          \
            int j = tid + p * 128;                                             \
            int row = j >> 2, ch = j & 3;                                      \
            uint32_t off = row * 64 + 16 * (ch ^ ((row >> 1) & 3));            \
            cpa16(st_ + off, Ag + (size_t)row * K + k0_ + ch * 8);             \
            cpa16(st_ + 8192 + off, Bg + (size_t)row * K + k0_ + ch * 8);      \
        }                                                                      \
        CP_COMMIT();                                                           \
    }

    LOADC(0, 0); LOADC(1, 1); LOADC(2, 2);

    int rA = lane & 15;
    int hA = lane >> 4;
    int rB = ((lane >> 4) << 3) + (lane & 7);
    int hB = (lane >> 3) & 1;

    uint32_t offA[4], xA[4], offB[4], xB[4];
    #pragma unroll
    for (int t4 = 0; t4 < 4; t4++) {
        int rowa = wm * 64 + t4 * 16 + rA;
        offA[t4] = rowa * 64;  xA[t4] = (rowa >> 1) & 3;
        int rowb = wn * 64 + t4 * 16 + rB;
        offB[t4] = rowb * 64;  xB[t4] = (rowb >> 1) & 3;
    }

    for (int c = 0; c < nch; c++) {
        CP_WAIT(2);
        __syncthreads();
        if (c + 3 < nch) { LOADC(c + 3, (c + 3) & 3); } else { CP_COMMIT(); }

        uint32_t abase = sbase + (c & 3) * STAGE_BYTES;
        uint32_t bbase = abase + 8192;

        #pragma unroll
        for (int ks = 0; ks < 2; ks++) {
            uint32_t afr[4][4];
            #pragma unroll
            for (int mt = 0; mt < 4; mt++) {
                uint32_t ad = abase + offA[mt] +
                              16 * (((uint32_t)(ks * 2 + hA)) ^ xA[mt]);
                LDMATRIX_X4(afr[mt][0], afr[mt][1], afr[mt][2], afr[mt][3], ad);
            }
            uint32_t bfr[8][2];
            #pragma unroll
            for (int pr = 0; pr < 4; pr++) {
                uint32_t bd = bbase + offB[pr] +
                              16 * (((uint32_t)(ks * 2 + hB)) ^ xB[pr]);
                uint32_t r0, r1, r2, r3;
                LDMATRIX_X4(r0, r1, r2, r3, bd);
                bfr[pr * 2][0] = r0;     bfr[pr * 2][1] = r1;
                bfr[pr * 2 + 1][0] = r2; bfr[pr * 2 + 1][1] = r3;
            }
            #pragma unroll
            for (int mt = 0; mt < 4; mt++)
                #pragma unroll
                for (int nt = 0; nt < 8; nt++)
                    MMA_F16(acc[mt][nt], afr[mt][0], afr[mt][1], afr[mt][2],
                            afr[mt][3], bfr[nt][0], bfr[nt][1]);
        }
    }

    int r0 = lane >> 2, c0 = lane & 3;
    #pragma unroll
    for (int mt = 0; mt < 4; mt++) {
        int row0 = bm * 128 + wm * 64 + mt * 16 + r0;
        #pragma unroll
        for (int nt = 0; nt < 8; nt++) {
            int col = bn * 128 + wn * 64 + nt * 8 + c0 * 2;
            float b0 = bias[col], b1 = bias[col + 1];
            float v00 = acc[mt][nt][0] + b0;
            float v01 = acc[mt][nt][1] + b1;
            float v10 = acc[mt][nt][2] + b0;
            float v11 = acc[mt][nt][3] + b1;
            if (EPI == 1) {
                float* C = (float*)Cv;
                const float* r0p = R + (size_t)row0 * N + col;
                const float* r1p = R + (size_t)(row0 + 8) * N + col;
                v00 += r0p[0]; v01 += r0p[1];
                v10 += r1p[0]; v11 += r1p[1];
                *(float2*)(C + (size_t)row0 * N + col) = make_float2(v00, v01);
                *(float2*)(C + (size_t)(row0 + 8) * N + col) = make_float2(v10, v11);
            } else if (EPI == 2) {
                __half* C = (__half*)Cv;
                __half2 o0 = __floats2half2_rn(gelu_tanh(v00), gelu_tanh(v01));
                __half2 o1 = __floats2half2_rn(gelu_tanh(v10), gelu_tanh(v11));
                *(__half2*)(C + (size_t)row0 * N + col) = o0;
                *(__half2*)(C + (size_t)(row0 + 8) * N + col) = o1;
            } else if (EPI == 3) {
                __half* C = (__half*)Cv;
                *(__half2*)(C + (size_t)row0 * N + col) = __floats2half2_rn(v00, v01);
                *(__half2*)(C + (size_t)(row0 + 8) * N + col) = __floats2half2_rn(v10, v11);
            } else {
                float* C = (float*)Cv;
                *(float2*)(C + (size_t)row0 * N + col) = make_float2(v00, v01);
                *(float2*)(C + (size_t)(row0 + 8) * N + col) = make_float2(v10, v11);
            }
        }
    }
    #undef LOADC
}

// =================== fp16 tensor-core GEMM 128x256 (wide N) ==================
// 256 threads, 8 warps (2x4), warp tile 64x64, BK=32, 4-stage.
// stage = A 8KB + B 16KB = 24KB; 4 stages = 96KB smem, 1 block/SM.
#define W_STAGE 24576
#define HW_SMEM (NSTAGE*W_STAGE)

template <int EPI>  // 2=+bias,gelu->f16  3=+bias->f16
__global__ __launch_bounds__(256, 1) void hgemm_w(
    const __half* __restrict__ A, const __half* __restrict__ BT,
    const float* __restrict__ bias, void* __restrict__ Cv,
    int M, int N, int K)
{
    extern __shared__ __align__(128) char smem[];
    uint32_t sbase = smem_u32(smem);
    int tid = threadIdx.x, lane = tid & 31, wid = tid >> 5;
    int wm = wid >> 2, wn = wid & 3;         // 2x4 warp grid
    int bm = blockIdx.y, bn = blockIdx.x;
    const __half* Ag = A  + (size_t)bm * 128 * K;
    const __half* Bg = BT + (size_t)bn * 256 * K;
    const int nch = K >> 5;

    float acc[4][8][4];
    #pragma unroll
    for (int i = 0; i < 4; i++)
        #pragma unroll
        for (int j = 0; j < 8; j++)
            #pragma unroll
            for (int q = 0; q < 4; q++) acc[i][j][q] = 0.f;

    // loader: A 512 chunks (2/thread), B 1024 chunks (4/thread)
    #define LOADW(c, s)                                                        \
    {                                                                          \
        uint32_t st_ = sbase + (s) * W_STAGE;                                  \
        int k0_ = (c) * 32;                                                    \
        _Pragma("unroll")                                                      \
        for (int p = 0; p < 2; p++) {                                          \
            int j = tid + p * 256;                                             \
            int row = j >> 2, ch = j & 3;                                      \
            uint32_t off = row * 64 + 16 * (ch ^ ((row >> 1) & 3));            \
            cpa16(st_ + off, Ag + (size_t)row * K + k0_ + ch * 8);             \
        }                                                                      \
        _Pragma("unroll")                                                      \
        for (int p = 0; p < 4; p++) {                                          \
            int j = tid + p * 256;                                             \
            int row = j >> 2, ch = j & 3;                                      \
            uint32_t off = row * 64 + 16 * (ch ^ ((row >> 1) & 3));            \
            cpa16(st_ + 8192 + off, Bg + (size_t)row * K + k0_ + ch * 8);      \
        }                                                                      \
        CP_COMMIT();                                                           \
    }

    LOADW(0, 0); LOADW(1, 1); LOADW(2, 2);

    int rA = lane & 15;
    int hA = lane >> 4;
    int rB = ((lane >> 4) << 3) + (lane & 7);
    int hB = (lane >> 3) & 1;

    uint32_t offA[4], xA[4], offB[4], xB[4];
    #pragma unroll
    for (int t4 = 0; t4 < 4; t4++) {
        int rowa = wm * 64 + t4 * 16 + rA;
        offA[t4] = rowa * 64;  xA[t4] = (rowa >> 1) & 3;
        int rowb = wn * 64 + t4 * 16 + rB;
        offB[t4] = rowb * 64;  xB[t4] = (rowb >> 1) & 3;
    }

    for (int c = 0; c < nch; c++) {
        CP_WAIT(2);
        __syncthreads();
        if (c + 3 < nch) { LOADW(c + 3, (c + 3) & 3); } else { CP_COMMIT(); }

        uint32_t abase = sbase + (c & 3) * W_STAGE;
        uint32_t bbase = abase + 8192;

        #pragma unroll
        for (int ks = 0; ks < 2; ks++) {
            uint32_t afr[4][4];
            #pragma unroll
            for (int mt = 0; mt < 4; mt++) {
                uint32_t ad = abase + offA[mt] +
                              16 * (((uint32_t)(ks * 2 + hA)) ^ xA[mt]);
                LDMATRIX_X4(afr[mt][0], afr[mt][1], afr[mt][2], afr[mt][3], ad);
            }
            uint32_t bfr[8][2];
            #pragma unroll
            for (int pr = 0; pr < 4; pr++) {
                uint32_t bd = bbase + offB[pr] +
                              16 * (((uint32_t)(ks * 2 + hB)) ^ xB[pr]);
                uint32_t r0, r1, r2, r3;
                LDMATRIX_X4(r0, r1, r2, r3, bd);
                bfr[pr * 2][0] = r0;     bfr[pr * 2][1] = r1;
                bfr[pr * 2 + 1][0] = r2; bfr[pr * 2 + 1][1] = r3;
            }
            #pragma unroll
            for (int mt = 0; mt < 4; mt++)
                #pragma unroll
                for (int nt = 0; nt < 8; nt++)
                    MMA_F16(acc[mt][nt], afr[mt][0], afr[mt][1], afr[mt][2],
                            afr[mt][3], bfr[nt][0], bfr[nt][1]);
        }
    }

    int r0 = lane >> 2, c0 = lane & 3;
    #pragma unroll
    for (int mt = 0; mt < 4; mt++) {
        int row0 = bm * 128 + wm * 64 + mt * 16 + r0;
        #pragma unroll
        for (int nt = 0; nt < 8; nt++) {
            int col = bn * 256 + wn * 64 + nt * 8 + c0 * 2;
            float b0 = bias[col], b1 = bias[col + 1];
            float v00 = acc[mt][nt][0] + b0;
            float v01 = acc[mt][nt][1] + b1;
            float v10 = acc[mt][nt][2] + b0;
            float v11 = acc[mt][nt][3] + b1;
            __half* C = (__half*)Cv;
            if (EPI == 2) {
                *(__half2*)(C + (size_t)row0 * N + col) =
                    __floats2half2_rn(gelu_tanh(v00), gelu_tanh(v01));
                *(__half2*)(C + (size_t)(row0 + 8) * N + col) =
                    __floats2half2_rn(gelu_tanh(v10), gelu_tanh(v11));
            } else {
                *(__half2*)(C + (size_t)row0 * N + col) = __floats2half2_rn(v00, v01);
                *(__half2*)(C + (size_t)(row0 + 8) * N + col) = __floats2half2_rn(v10, v11);
            }
        }
    }
    #undef LOADW
}

// ================= fp16 tensor-core flash attention =================
#define AT_SMEM (8192 + 2*16384)   // Q + 2 stages of (K+V)

__global__ __launch_bounds__(128) void attn_mma(
    const __half* __restrict__ qkv, __half* __restrict__ y)
{
    extern __shared__ __align__(128) char smem[];
    uint32_t sb = smem_u32(smem);
    int tid = threadIdx.x, lane = tid & 31, w = tid >> 5;
    int qt = blockIdx.x;
    int bh = blockIdx.y;
    int b = bh / HEADS, h = bh - (bh / HEADS) * HEADS;
    const __half* base = qkv + (size_t)b * TSEQ * C3;
    int qcol = h * DHEAD, kcol = CDIM + h * DHEAD, vcol = 2 * CDIM + h * DHEAD;

    #define SWOFF(row, ch) ((uint32_t)((row) * 128 + 16 * ((ch) ^ ((row) & 7))))

    {
        #pragma unroll
        for (int p = 0; p < 4; p++) {
            int j = tid + p * 128;
            int row = j >> 3, ch = j & 7;
            cpa16(sb + SWOFF(row, ch),
                  base + (size_t)(qt * 64 + row) * C3 + qcol + ch * 8);
        }
    }
    #define LOADKV(kt, s)                                                      \
    {                                                                          \
        uint32_t kb_ = sb + 8192 + (s) * 16384;                                \
        _Pragma("unroll")                                                      \
        for (int p = 0; p < 4; p++) {                                          \
            int j = tid + p * 128;                                             \
            int row = j >> 3, ch = j & 7;                                      \
            const __half* rp = base + (size_t)((kt) * 64 + row) * C3;          \
            cpa16(kb_ + SWOFF(row, ch), rp + kcol + ch * 8);                   \
            cpa16(kb_ + 8192 + SWOFF(row, ch), rp + vcol + ch * 8);            \
        }                                                                      \
    }
    LOADKV(0, 0);
    CP_COMMIT();

    float m0 = -1e30f, m1 = -1e30f, l0 = 0.f, l1 = 0.f;
    float o[8][4];
    #pragma unroll
    for (int i = 0; i < 8; i++)
        #pragma unroll
        for (int q = 0; q < 4; q++) o[i][q] = 0.f;

    uint32_t qfr[4][4];
    int rqA = w * 16 + (lane & 15);
    int hA  = lane >> 4;
    int rB  = ((lane >> 4) << 3) + (lane & 7);
    int hB  = (lane >> 3) & 1;
    int rV  = ((lane >> 3) & 1) * 8 + (lane & 7);
    int hV  = lane >> 4;

    int r0loc = (lane >> 2);
    int r0g = qt * 64 + w * 16 + r0loc;
    int cq = lane & 3;

    for (int kt = 0; kt <= qt; kt++) {
        __syncthreads();
        if (kt + 1 <= qt) { LOADKV(kt + 1, (kt + 1) & 1); CP_COMMIT(); }
        else { CP_COMMIT(); }
        CP_WAIT(1);
        __syncthreads();

        if (kt == 0) {
            #pragma unroll
            for (int ks = 0; ks < 4; ks++) {
                uint32_t ad = sb + (uint32_t)(rqA * 128 +
                              16 * ((ks * 2 + hA) ^ (rqA & 7)));
                LDMATRIX_X4(qfr[ks][0], qfr[ks][1], qfr[ks][2], qfr[ks][3], ad);
            }
        }

        uint32_t kb = sb + 8192 + (kt & 1) * 16384;
        uint32_t vb = kb + 8192;

        float s_acc[8][4];
        #pragma unroll
        for (int i = 0; i < 8; i++)
            #pragma unroll
            for (int q = 0; q < 4; q++) s_acc[i][q] = 0.f;

        #pragma unroll
        for (int ks = 0; ks < 4; ks++) {
            #pragma unroll
            for (int pr = 0; pr < 4; pr++) {
                int row = pr * 16 + rB;
                uint32_t bd = kb + (uint32_t)(row * 128 +
                              16 * ((ks * 2 + hB) ^ (row & 7)));
                uint32_t b0, b1, b2, b3;
                LDMATRIX_X4(b0, b1, b2, b3, bd);
                MMA_F16(s_acc[pr * 2],     qfr[ks][0], qfr[ks][1], qfr[ks][2], qfr[ks][3], b0, b1);
                MMA_F16(s_acc[pr * 2 + 1], qfr[ks][0], qfr[ks][1], qfr[ks][2], qfr[ks][3], b2, b3);
            }
        }

        bool diag = (kt == qt);
        float mx0 = -1e30f, mx1 = -1e30f;
        #pragma unroll
        for (int nt = 0; nt < 8; nt++) {
            #pragma unroll
            for (int j = 0; j < 2; j++) {
                int col = kt * 64 + nt * 8 + cq * 2 + j;
                float s0 = s_acc[nt][j] * 0.125f;
                float s1 = s_acc[nt][2 + j] * 0.125f;
                if (diag && col > r0g)     s0 = -1e30f;
                if (diag && col > r0g + 8) s1 = -1e30f;
                s_acc[nt][j] = s0; s_acc[nt][2 + j] = s1;
                mx0 = fmaxf(mx0, s0); mx1 = fmaxf(mx1, s1);
            }
        }
        mx0 = fmaxf(mx0, __shfl_xor_sync(0xffffffffu, mx0, 1));
        mx0 = fmaxf(mx0, __shfl_xor_sync(0xffffffffu, mx0, 2));
        mx1 = fmaxf(mx1, __shfl_xor_sync(0xffffffffu, mx1, 1));
        mx1 = fmaxf(mx1, __shfl_xor_sync(0xffffffffu, mx1, 2));
        float mn0 = fmaxf(m0, mx0), mn1 = fmaxf(m1, mx1);
        float a0 = __expf(m0 - mn0), a1 = __expf(m1 - mn1);
        float sum0 = 0.f, sum1 = 0.f;
        #pragma unroll
        for (int nt = 0; nt < 8; nt++) {
            #pragma unroll
            for (int j = 0; j < 2; j++) {
                float p0 = __expf(s_acc[nt][j] - mn0);
                float p1 = __expf(s_acc[nt][2 + j] - mn1);
                s_acc[nt][j] = p0; s_acc[nt][2 + j] = p1;
                sum0 += p0; sum1 += p1;
            }
        }
        sum0 += __shfl_xor_sync(0xffffffffu, sum0, 1);
        sum0 += __shfl_xor_sync(0xffffffffu, sum0, 2);
        sum1 += __shfl_xor_sync(0xffffffffu, sum1, 1);
        sum1 += __shfl_xor_sync(0xffffffffu, sum1, 2);
        l0 = l0 * a0 + sum0; l1 = l1 * a1 + sum1;
        m0 = mn0; m1 = mn1;

        #pragma unroll
        for (int nt = 0; nt < 8; nt++) {
            o[nt][0] *= a0; o[nt][1] *= a0;
            o[nt][2] *= a1; o[nt][3] *= a1;
        }

        uint32_t pa[4][4];
        #pragma unroll
        for (int kv = 0; kv < 4; kv++) {
            pa[kv][0] = packh2(s_acc[2 * kv][0],     s_acc[2 * kv][1]);
            pa[kv][1] = packh2(s_acc[2 * kv][2],     s_acc[2 * kv][3]);
            pa[kv][2] = packh2(s_acc[2 * kv + 1][0], s_acc[2 * kv + 1][1]);
            pa[kv][3] = packh2(s_acc[2 * kv + 1][2], s_acc[2 * kv + 1][3]);
        }

        #pragma unroll
        for (int kv = 0; kv < 4; kv++) {
            #pragma unroll
            for (int dt = 0; dt < 4; dt++) {
                int row = kv * 16 + rV;
                uint32_t vd = vb + (uint32_t)(row * 128 +
                              16 * ((dt * 2 + hV) ^ (row & 7)));
                uint32_t b0, b1, b2, b3;
                LDMATRIX_X4_T(b0, b1, b2, b3, vd);
                MMA_F16(o[dt * 2],     pa[kv][0], pa[kv][1], pa[kv][2], pa[kv][3], b0, b1);
                MMA_F16(o[dt * 2 + 1], pa[kv][0], pa[kv][1], pa[kv][2], pa[kv][3], b2, b3);
            }
        }
    }

    float inv0 = 1.f / l0, inv1 = 1.f / l1;
    size_t row0 = (size_t)b * TSEQ + qt * 64 + w * 16 + r0loc;
    __half* y0 = y + row0 * CDIM + h * DHEAD + cq * 2;
    __half* y1 = y0 + 8 * CDIM;
    #pragma unroll
    for (int nt = 0; nt < 8; nt++) {
        *(__half2*)(y0 + nt * 8) = __floats2half2_rn(o[nt][0] * inv0, o[nt][1] * inv0);
        *(__half2*)(y1 + nt * 8) = __floats2half2_rn(o[nt][2] * inv1, o[nt][3] * inv1);
    }
    #undef LOADKV
    #undef SWOFF
}

// ---------------- launch ----------------
extern "C" void kernel_launch(void* const* d_in, const int* in_sizes, int n_in,
                              void* d_out, int out_size)
{
    const int*   idx    = (const int*)  d_in[0];
    const float* wte    = (const float*)d_in[1];
    const float* wpe    = (const float*)d_in[2];
    const float* ln1_w  = (const float*)d_in[3];
    const float* ln1_b  = (const float*)d_in[4];
    const float* w_qkv  = (const float*)d_in[5];
    const float* b_qkv  = (const float*)d_in[6];
    const float* w_ao   = (const float*)d_in[7];
    const float* b_ao   = (const float*)d_in[8];
    const float* ln2_w  = (const float*)d_in[9];
    const float* ln2_b  = (const float*)d_in[10];
    const float* w_fc   = (const float*)d_in[11];
    const float* b_fc   = (const float*)d_in[12];
    const float* w_fp   = (const float*)d_in[13];
    const float* b_fp   = (const float*)d_in[14];
    const float* lnf_w  = (const float*)d_in[15];
    const float* lnf_b  = (const float*)d_in[16];
    const float* w_head = (const float*)d_in[17];
    float* out = (float*)d_out;

    float *x;
    __half *qkvh, *hh, *yh, *fch, *wqkvT, *waoT, *wfcT, *wfpT;
    cudaGetSymbolAddress((void**)&x,    g_x);
    cudaGetSymbolAddress((void**)&qkvh, g_qkv);
    cudaGetSymbolAddress((void**)&hh,   g_h);
    cudaGetSymbolAddress((void**)&yh,   g_y);
    cudaGetSymbolAddress((void**)&fch,  g_fc);
    cudaGetSymbolAddress((void**)&wqkvT, g_wqkvT);
    cudaGetSymbolAddress((void**)&waoT,  g_waoT);
    cudaGetSymbolAddress((void**)&wfcT,  g_wfcT);
    cudaGetSymbolAddress((void**)&wfpT,  g_wfpT);

    cudaFuncSetAttribute(attn_mma, cudaFuncAttributeMaxDynamicSharedMemorySize, AT_SMEM);
    cudaFuncSetAttribute(hgemm<1>, cudaFuncAttributeMaxDynamicSharedMemorySize, HG_SMEM);
    cudaFuncSetAttribute(hgemm_w<2>, cudaFuncAttributeMaxDynamicSharedMemorySize, HW_SMEM);
    cudaFuncSetAttribute(hgemm_w<3>, cudaFuncAttributeMaxDynamicSharedMemorySize, HW_SMEM);

    transpose_kernel<<<dim3(C3 / 32, CDIM / 32, LAYERS), 256>>>(w_qkv, wqkvT, CDIM, C3);
    transpose_kernel<<<dim3(CDIM / 32, CDIM / 32, LAYERS), 256>>>(w_ao, waoT, CDIM, CDIM);
    transpose_kernel<<<dim3(C4 / 32, CDIM / 32, LAYERS), 256>>>(w_fc, wfcT, CDIM, C4);
    transpose_kernel<<<dim3(CDIM / 32, C4 / 32, LAYERS), 256>>>(w_fp, wfpT, C4, CDIM);

    embed_kernel<<<(MROWS * CDIM) / 256, 256>>>(idx, wte, wpe, x);

    for (int l = 0; l < LAYERS; l++) {
        ln_kernel<<<MROWS, 256>>>(x, ln1_w + l * CDIM, ln1_b + l * CDIM, hh);
        hgemm_w<3><<<dim3(C3 / 256, MROWS / 128), 256, HW_SMEM>>>(
            hh, wqkvT + (size_t)l * C3 * CDIM, b_qkv + l * C3, qkvh,
            MROWS, C3, CDIM);
        attn_mma<<<dim3(TSEQ / 64, BATCH * HEADS), 128, AT_SMEM>>>(qkvh, yh);
        hgemm<1><<<dim3(CDIM / 128, MROWS / 128), 128, HG_SMEM>>>(
            yh, waoT + (size_t)l * CDIM * CDIM, b_ao + l * CDIM, x, x,
            MROWS, CDIM, CDIM);
        ln_kernel<<<MROWS, 256>>>(x, ln2_w + l * CDIM, ln2_b + l * CDIM, hh);
        hgemm_w<2><<<dim3(C4 / 256, MROWS / 128), 256, HW_SMEM>>>(
            hh, wfcT + (size_t)l * C4 * CDIM, b_fc + l * C4, fch,
            MROWS, C4, CDIM);
        hgemm<1><<<dim3(CDIM / 128, MROWS / 128), 128, HG_SMEM>>>(
            fch, wfpT + (size_t)l * CDIM * C4, b_fp + l * CDIM, x, x,
            MROWS, CDIM, C4);
    }

    head_kernel<<<MROWS, 256>>>(x, lnf_w, lnf_b, w_head, out);
}

// round 8
// speedup vs baseline: 1.1617x; 1.1617x over previous
#include <cuda_runtime.h>
#include <cuda_fp16.h>
#include <math.h>
#include <stdint.h>

// ---------------- problem constants ----------------
#define LAYERS 12
#define HEADS  12
#define CDIM   768
#define TSEQ   1024
#define BATCH  4
#define MROWS  (BATCH*TSEQ)      // 4096
#define C3     (3*CDIM)          // 2304
#define C4     (4*CDIM)          // 3072
#define DHEAD  64

// ---------------- scratch (device globals: no allocation allowed) ----------
__device__ float  g_x  [MROWS*CDIM];          // fp32 residual stream
__device__ __half g_qkv[MROWS*C3];            // fp16 qkv
__device__ __half g_h  [MROWS*CDIM];          // fp16 LN output (GEMM A)
__device__ __half g_y  [MROWS*CDIM];          // fp16 attention output
__device__ __half g_fc [MROWS*C4];            // fp16 gelu output
// transposed (to [N,K] K-major) fp16 weights
__device__ __half g_wqkvT[LAYERS*C3*CDIM];
__device__ __half g_waoT [LAYERS*CDIM*CDIM];
__device__ __half g_wfcT [LAYERS*C4*CDIM];
__device__ __half g_wfpT [LAYERS*CDIM*C4];

// ---------------- helpers ----------------
__device__ __forceinline__ uint32_t smem_u32(const void* p) {
    uint32_t a;
    asm("{ .reg .u64 t; cvta.to.shared.u64 t, %1; cvt.u32.u64 %0, t; }"
        : "=r"(a) : "l"(p));
    return a;
}
__device__ __forceinline__ void cpa16(uint32_t saddr, const void* g) {
    asm volatile("cp.async.cg.shared.global [%0], [%1], 16;" :: "r"(saddr), "l"(g));
}
#define CP_COMMIT()  asm volatile("cp.async.commit_group;" ::: "memory")
#define CP_WAIT(n)   asm volatile("cp.async.wait_group %0;" :: "n"(n) : "memory")

#define LDMATRIX_X4(r0, r1, r2, r3, addr) \
    asm volatile("ldmatrix.sync.aligned.m8n8.x4.shared.b16 {%0,%1,%2,%3}, [%4];" \
        : "=r"(r0), "=r"(r1), "=r"(r2), "=r"(r3) : "r"(addr))

#define LDMATRIX_X4_T(r0, r1, r2, r3, addr) \
    asm volatile("ldmatrix.sync.aligned.m8n8.x4.trans.shared.b16 {%0,%1,%2,%3}, [%4];" \
        : "=r"(r0), "=r"(r1), "=r"(r2), "=r"(r3) : "r"(addr))

#define MMA_F16(d, a0, a1, a2, a3, b0, b1) \
    asm volatile( \
        "mma.sync.aligned.m16n8k16.row.col.f32.f16.f16.f32 " \
        "{%0,%1,%2,%3},{%4,%5,%6,%7},{%8,%9},{%0,%1,%2,%3};" \
        : "+f"((d)[0]), "+f"((d)[1]), "+f"((d)[2]), "+f"((d)[3]) \
        : "r"(a0), "r"(a1), "r"(a2), "r"(a3), "r"(b0), "r"(b1))

__device__ __forceinline__ uint32_t packh2(float lo, float hi) {
    __half2 h = __floats2half2_rn(lo, hi);
    return *(uint32_t*)&h;
}

__device__ __forceinline__ float gelu_tanh(float v) {
    float c = 0.7978845608028654f * (v + 0.044715f * v * v * v);
    return 0.5f * v * (1.0f + tanhf(c));
}

// ---------------- embedding ----------------
__global__ __launch_bounds__(256) void embed_kernel(
    const int* __restrict__ idx, const float* __restrict__ wte,
    const float* __restrict__ wpe, float* __restrict__ x)
{
    int i = blockIdx.x * 256 + threadIdx.x;
    int row = i / CDIM;
    int c   = i - row * CDIM;
    int t   = row & (TSEQ - 1);
    int id  = idx[row];
    x[i] = wte[(size_t)id * CDIM + c] + wpe[(size_t)t * CDIM + c];
}

// ------------- weight transpose 64x64 (fp32 [K,N] -> fp16 [N,K]) ------------
__global__ __launch_bounds__(256) void transpose_kernel(
    const float* __restrict__ W, __half* __restrict__ WT, int K, int N)
{
    __shared__ float t[64][65];
    int l = blockIdx.z;
    const float* Wl = W + (size_t)l * K * N;
    __half* WTl = WT + (size_t)l * N * K;
    int k0 = blockIdx.y * 64, n0 = blockIdx.x * 64;

    int tx = threadIdx.x & 15, ty = threadIdx.x >> 4;   // 16 x 16, float4
    #pragma unroll
    for (int r = ty; r < 64; r += 16) {
        float4 v = *(const float4*)(Wl + (size_t)(k0 + r) * N + n0 + tx * 4);
        t[r][tx * 4 + 0] = v.x;
        t[r][tx * 4 + 1] = v.y;
        t[r][tx * 4 + 2] = v.z;
        t[r][tx * 4 + 3] = v.w;
    }
    __syncthreads();
    int lx = threadIdx.x & 31, ly = threadIdx.x >> 5;   // 32 x 8, half2
    #pragma unroll
    for (int r = ly; r < 64; r += 8) {
        __half2 h = __floats2half2_rn(t[lx * 2][r], t[lx * 2 + 1][r]);
        *(__half2*)(WTl + (size_t)(n0 + r) * K + k0 + lx * 2) = h;
    }
}

// ---------------- layernorm (fp16 output) ----------------
__global__ __launch_bounds__(256) void ln_kernel(
    const float* __restrict__ x, const float* __restrict__ w,
    const float* __restrict__ b, __half* __restrict__ out)
{
    int row = blockIdx.x;
    const float* xr = x + (size_t)row * CDIM;
    float s = 0.f, s2 = 0.f;
    for (int i = threadIdx.x; i < CDIM; i += 256) {
        float v = xr[i]; s += v; s2 += v * v;
    }
    #pragma unroll
    for (int o = 16; o; o >>= 1) {
        s  += __shfl_xor_sync(0xffffffffu, s,  o);
        s2 += __shfl_xor_sync(0xffffffffu, s2, o);
    }
    __shared__ float rbuf[16];
    int wid = threadIdx.x >> 5, lane = threadIdx.x & 31;
    if (lane == 0) { rbuf[wid] = s; rbuf[8 + wid] = s2; }
    __syncthreads();
    float ts = 0.f, ts2 = 0.f;
    #pragma unroll
    for (int i = 0; i < 8; i++) { ts += rbuf[i]; ts2 += rbuf[8 + i]; }
    float mu  = ts * (1.0f / CDIM);
    float var = ts2 * (1.0f / CDIM) - mu * mu;
    float rs  = rsqrtf(var + 1e-5f);
    __half* orow = out + (size_t)row * CDIM;
    for (int i = threadIdx.x; i < CDIM; i += 256) {
        orow[i] = __float2half_rn((xr[i] - mu) * rs * w[i] + b[i]);
    }
}

// ---------------- final LN + head matvec ----------------
__global__ __launch_bounds__(256) void head_kernel(
    const float* __restrict__ x, const float* __restrict__ lw,
    const float* __restrict__ lb, const float* __restrict__ wh,
    float* __restrict__ out)
{
    int row = blockIdx.x;
    const float* xr = x + (size_t)row * CDIM;
    float s = 0.f, s2 = 0.f;
    for (int i = threadIdx.x; i < CDIM; i += 256) {
        float v = xr[i]; s += v; s2 += v * v;
    }
    #pragma unroll
    for (int o = 16; o; o >>= 1) {
        s  += __shfl_xor_sync(0xffffffffu, s,  o);
        s2 += __shfl_xor_sync(0xffffffffu, s2, o);
    }
    __shared__ float rbuf[16];
    int wid = threadIdx.x >> 5, lane = threadIdx.x & 31;
    if (lane == 0) { rbuf[wid] = s; rbuf[8 + wid] = s2; }
    __syncthreads();
    float ts = 0.f, ts2 = 0.f;
    #pragma unroll
    for (int i = 0; i < 8; i++) { ts += rbuf[i]; ts2 += rbuf[8 + i]; }
    float mu  = ts * (1.0f / CDIM);
    float var = ts2 * (1.0f / CDIM) - mu * mu;
    float rs  = rsqrtf(var + 1e-5f);

    float acc = 0.f;
    for (int i = threadIdx.x; i < CDIM; i += 256) {
        float hn = (xr[i] - mu) * rs * lw[i] + lb[i];
        acc += hn * wh[i];
    }
    #pragma unroll
    for (int o = 16; o; o >>= 1) acc += __shfl_xor_sync(0xffffffffu, acc, o);
    __syncthreads();
    if (lane == 0) rbuf[wid] = acc;
    __syncthreads();
    if (threadIdx.x == 0) {
        float t = 0.f;
        #pragma unroll
        for (int i = 0; i < 8; i++) t += rbuf[i];
        out[row] = t;
    }
}

// ======================= fp16 tensor-core GEMM (mma.sync) ====================
// Block (MT*32)x128, BK=32, 4 warps (2x2), warp tile (MT*16)x64, 4-stage.
// MT=4: 128-row blocks (QKV/FC). MT=2: 64-row blocks (proj/FP, better waves).
#define NSTAGE 4

template <int EPI, int MT>  // EPI: 0=+bias->f32 1=+bias+res->f32 2=gelu->f16 3=->f16
__global__ __launch_bounds__(128, 2) void hgemm(
    const __half* __restrict__ A, const __half* __restrict__ BT,
    const float* __restrict__ bias, const float* __restrict__ R,
    void* __restrict__ Cv, int M, int N, int K)
{
    constexpr int AROWS  = MT * 32;             // block M
    constexpr int ABYTES = AROWS * 64;          // A stage bytes
    constexpr int STAGE  = ABYTES + 8192;       // + B 8KB
    extern __shared__ __align__(128) char smem[];
    uint32_t sbase = smem_u32(smem);
    int tid = threadIdx.x, lane = tid & 31, wid = tid >> 5;
    int wm = wid >> 1, wn = wid & 1;
    int bm = blockIdx.y, bn = blockIdx.x;
    const __half* Ag = A  + (size_t)bm * AROWS * K;
    const __half* Bg = BT + (size_t)bn * 128 * K;
    const int nch = K >> 5;

    float acc[MT][8][4];
    #pragma unroll
    for (int i = 0; i < MT; i++)
        #pragma unroll
        for (int j = 0; j < 8; j++)
            #pragma unroll
            for (int q = 0; q < 4; q++) acc[i][j][q] = 0.f;

    #define LOADC(c, s)                                                        \
    {                                                                          \
        uint32_t st_ = sbase + (s) * STAGE;                                    \
        int k0_ = (c) * 32;                                                    \
        _Pragma("unroll")                                                      \
        for (int p = 0; p < MT; p++) {                                         \
            int j = tid + p * 128;                                             \
            int row = j >> 2, ch = j & 3;                                      \
            uint32_t off = row * 64 + 16 * (ch ^ ((row >> 1) & 3));            \
            cpa16(st_ + off, Ag + (size_t)row * K + k0_ + ch * 8);             \
        }                                                                      \
        _Pragma("unroll")                                                      \
        for (int p = 0; p < 4; p++) {                                          \
            int j = tid + p * 128;                                             \
            int row = j >> 2, ch = j & 3;                                      \
            uint32_t off = row * 64 + 16 * (ch ^ ((row >> 1) & 3));            \
            cpa16(st_ + ABYTES + off, Bg + (size_t)row * K + k0_ + ch * 8);    \
        }                                                                      \
        CP_COMMIT();                                                           \
    }

    LOADC(0, 0); LOADC(1, 1); LOADC(2, 2);

    int rA = lane & 15;
    int hA = lane >> 4;
    int rB = ((lane >> 4) << 3) + (lane & 7);
    int hB = (lane >> 3) & 1;

    uint32_t offA[MT], xA[MT], offB[4], xB[4];
    #pragma unroll
    for (int t4 = 0; t4 < MT; t4++) {
        int rowa = wm * (MT * 16) + t4 * 16 + rA;
        offA[t4] = rowa * 64;  xA[t4] = (rowa >> 1) & 3;
    }
    #pragma unroll
    for (int t4 = 0; t4 < 4; t4++) {
        int rowb = wn * 64 + t4 * 16 + rB;
        offB[t4] = rowb * 64;  xB[t4] = (rowb >> 1) & 3;
    }

    for (int c = 0; c < nch; c++) {
        CP_WAIT(2);
        __syncthreads();
        if (c + 3 < nch) { LOADC(c + 3, (c + 3) & 3); } else { CP_COMMIT(); }

        uint32_t abase = sbase + (c & 3) * STAGE;
        uint32_t bbase = abase + ABYTES;

        #pragma unroll
        for (int ks = 0; ks < 2; ks++) {
            uint32_t afr[MT][4];
            #pragma unroll
            for (int mt = 0; mt < MT; mt++) {
                uint32_t ad = abase + offA[mt] +
                              16 * (((uint32_t)(ks * 2 + hA)) ^ xA[mt]);
                LDMATRIX_X4(afr[mt][0], afr[mt][1], afr[mt][2], afr[mt][3], ad);
            }
            uint32_t bfr[8][2];
            #pragma unroll
            for (int pr = 0; pr < 4; pr++) {
                uint32_t bd = bbase + offB[pr] +
                              16 * (((uint32_t)(ks * 2 + hB)) ^ xB[pr]);
                uint32_t r0, r1, r2, r3;
                LDMATRIX_X4(r0, r1, r2, r3, bd);
                bfr[pr * 2][0] = r0;     bfr[pr * 2][1] = r1;
                bfr[pr * 2 + 1][0] = r2; bfr[pr * 2 + 1][1] = r3;
            }
            #pragma unroll
            for (int mt = 0; mt < MT; mt++)
                #pragma unroll
                for (int nt = 0; nt < 8; nt++)
                    MMA_F16(acc[mt][nt], afr[mt][0], afr[mt][1], afr[mt][2],
                            afr[mt][3], bfr[nt][0], bfr[nt][1]);
        }
    }

    int r0 = lane >> 2, c0 = lane & 3;
    #pragma unroll
    for (int mt = 0; mt < MT; mt++) {
        int row0 = bm * AROWS + wm * (MT * 16) + mt * 16 + r0;
        #pragma unroll
        for (int nt = 0; nt < 8; nt++) {
            int col = bn * 128 + wn * 64 + nt * 8 + c0 * 2;
            float b0 = bias[col], b1 = bias[col + 1];
            float v00 = acc[mt][nt][0] + b0;
            float v01 = acc[mt][nt][1] + b1;
            float v10 = acc[mt][nt][2] + b0;
            float v11 = acc[mt][nt][3] + b1;
            if (EPI == 1) {
                float* C = (float*)Cv;
                const float* r0p = R + (size_t)row0 * N + col;
                const float* r1p = R + (size_t)(row0 + 8) * N + col;
                v00 += r0p[0]; v01 += r0p[1];
                v10 += r1p[0]; v11 += r1p[1];
                *(float2*)(C + (size_t)row0 * N + col) = make_float2(v00, v01);
                *(float2*)(C + (size_t)(row0 + 8) * N + col) = make_float2(v10, v11);
            } else if (EPI == 2) {
                __half* C = (__half*)Cv;
                __half2 o0 = __floats2half2_rn(gelu_tanh(v00), gelu_tanh(v01));
                __half2 o1 = __floats2half2_rn(gelu_tanh(v10), gelu_tanh(v11));
                *(__half2*)(C + (size_t)row0 * N + col) = o0;
                *(__half2*)(C + (size_t)(row0 + 8) * N + col) = o1;
            } else if (EPI == 3) {
                __half* C = (__half*)Cv;
                *(__half2*)(C + (size_t)row0 * N + col) = __floats2half2_rn(v00, v01);
                *(__half2*)(C + (size_t)(row0 + 8) * N + col) = __floats2half2_rn(v10, v11);
            } else {
                float* C = (float*)Cv;
                *(float2*)(C + (size_t)row0 * N + col) = make_float2(v00, v01);
                *(float2*)(C + (size_t)(row0 + 8) * N + col) = make_float2(v10, v11);
            }
        }
    }
    #undef LOADC
}

#define HG_SMEM4 (NSTAGE * (128*64 + 8192))   // MT=4: 65536
#define HG_SMEM2 (NSTAGE * (64*64 + 8192))    // MT=2: 49152

// ================= fp16 tensor-core flash attention =================
#define AT_SMEM (8192 + 2*16384)   // Q + 2 stages of (K+V)

__global__ __launch_bounds__(128) void attn_mma(
    const __half* __restrict__ qkv, __half* __restrict__ y)
{
    extern __shared__ __align__(128) char smem[];
    uint32_t sb = smem_u32(smem);
    int tid = threadIdx.x, lane = tid & 31, w = tid >> 5;
    int qt = blockIdx.x;
    int bh = blockIdx.y;
    int b = bh / HEADS, h = bh - (bh / HEADS) * HEADS;
    const __half* base = qkv + (size_t)b * TSEQ * C3;
    int qcol = h * DHEAD, kcol = CDIM + h * DHEAD, vcol = 2 * CDIM + h * DHEAD;

    #define SWOFF(row, ch) ((uint32_t)((row) * 128 + 16 * ((ch) ^ ((row) & 7))))

    {
        #pragma unroll
        for (int p = 0; p < 4; p++) {
            int j = tid + p * 128;
            int row = j >> 3, ch = j & 7;
            cpa16(sb + SWOFF(row, ch),
                  base + (size_t)(qt * 64 + row) * C3 + qcol + ch * 8);
        }
    }
    #define LOADKV(kt, s)                                                      \
    {                                                                          \
        uint32_t kb_ = sb + 8192 + (s) * 16384;                                \
        _Pragma("unroll")                                                      \
        for (int p = 0; p < 4; p++) {                                          \
            int j = tid + p * 128;                                             \
            int row = j >> 3, ch = j & 7;                                      \
            const __half* rp = base + (size_t)((kt) * 64 + row) * C3;          \
            cpa16(kb_ + SWOFF(row, ch), rp + kcol + ch * 8);                   \
            cpa16(kb_ + 8192 + SWOFF(row, ch), rp + vcol + ch * 8);            \
        }                                                                      \
    }
    LOADKV(0, 0);
    CP_COMMIT();

    float m0 = -1e30f, m1 = -1e30f, l0 = 0.f, l1 = 0.f;
    float o[8][4];
    #pragma unroll
    for (int i = 0; i < 8; i++)
        #pragma unroll
        for (int q = 0; q < 4; q++) o[i][q] = 0.f;

    uint32_t qfr[4][4];
    int rqA = w * 16 + (lane & 15);
    int hA  = lane >> 4;
    int rB  = ((lane >> 4) << 3) + (lane & 7);
    int hB  = (lane >> 3) & 1;
    int rV  = ((lane >> 3) & 1) * 8 + (lane & 7);
    int hV  = lane >> 4;

    int r0loc = (lane >> 2);
    int r0g = qt * 64 + w * 16 + r0loc;
    int cq = lane & 3;

    for (int kt = 0; kt <= qt; kt++) {
        __syncthreads();
        if (kt + 1 <= qt) { LOADKV(kt + 1, (kt + 1) & 1); CP_COMMIT(); }
        else { CP_COMMIT(); }
        CP_WAIT(1);
        __syncthreads();

        if (kt == 0) {
            #pragma unroll
            for (int ks = 0; ks < 4; ks++) {
                uint32_t ad = sb + (uint32_t)(rqA * 128 +
                              16 * ((ks * 2 + hA) ^ (rqA & 7)));
                LDMATRIX_X4(qfr[ks][0], qfr[ks][1], qfr[ks][2], qfr[ks][3], ad);
            }
        }

        uint32_t kb = sb + 8192 + (kt & 1) * 16384;
        uint32_t vb = kb + 8192;

        float s_acc[8][4];
        #pragma unroll
        for (int i = 0; i < 8; i++)
            #pragma unroll
            for (int q = 0; q < 4; q++) s_acc[i][q] = 0.f;

        #pragma unroll
        for (int ks = 0; ks < 4; ks++) {
            #pragma unroll
            for (int pr = 0; pr < 4; pr++) {
                int row = pr * 16 + rB;
                uint32_t bd = kb + (uint32_t)(row * 128 +
                              16 * ((ks * 2 + hB) ^ (row & 7)));
                uint32_t b0, b1, b2, b3;
                LDMATRIX_X4(b0, b1, b2, b3, bd);
                MMA_F16(s_acc[pr * 2],     qfr[ks][0], qfr[ks][1], qfr[ks][2], qfr[ks][3], b0, b1);
                MMA_F16(s_acc[pr * 2 + 1], qfr[ks][0], qfr[ks][1], qfr[ks][2], qfr[ks][3], b2, b3);
            }
        }

        bool diag = (kt == qt);
        float mx0 = -1e30f, mx1 = -1e30f;
        #pragma unroll
        for (int nt = 0; nt < 8; nt++) {
            #pragma unroll
            for (int j = 0; j < 2; j++) {
                int col = kt * 64 + nt * 8 + cq * 2 + j;
                float s0 = s_acc[nt][j] * 0.125f;
                float s1 = s_acc[nt][2 + j] * 0.125f;
                if (diag && col > r0g)     s0 = -1e30f;
                if (diag && col > r0g + 8) s1 = -1e30f;
                s_acc[nt][j] = s0; s_acc[nt][2 + j] = s1;
                mx0 = fmaxf(mx0, s0); mx1 = fmaxf(mx1, s1);
            }
        }
        mx0 = fmaxf(mx0, __shfl_xor_sync(0xffffffffu, mx0, 1));
        mx0 = fmaxf(mx0, __shfl_xor_sync(0xffffffffu, mx0, 2));
        mx1 = fmaxf(mx1, __shfl_xor_sync(0xffffffffu, mx1, 1));
        mx1 = fmaxf(mx1, __shfl_xor_sync(0xffffffffu, mx1, 2));
        float mn0 = fmaxf(m0, mx0), mn1 = fmaxf(m1, mx1);
        float a0 = __expf(m0 - mn0), a1 = __expf(m1 - mn1);
        float sum0 = 0.f, sum1 = 0.f;
        #pragma unroll
        for (int nt = 0; nt < 8; nt++) {
            #pragma unroll
            for (int j = 0; j < 2; j++) {
                float p0 = __expf(s_acc[nt][j] - mn0);
                float p1 = __expf(s_acc[nt][2 + j] - mn1);
                s_acc[nt][j] = p0; s_acc[nt][2 + j] = p1;
                sum0 += p0; sum1 += p1;
            }
        }
        sum0 += __shfl_xor_sync(0xffffffffu, sum0, 1);
        sum0 += __shfl_xor_sync(0xffffffffu, sum0, 2);
        sum1 += __shfl_xor_sync(0xffffffffu, sum1, 1);
        sum1 += __shfl_xor_sync(0xffffffffu, sum1, 2);
        l0 = l0 * a0 + sum0; l1 = l1 * a1 + sum1;
        m0 = mn0; m1 = mn1;

        #pragma unroll
        for (int nt = 0; nt < 8; nt++) {
            o[nt][0] *= a0; o[nt][1] *= a0;
            o[nt][2] *= a1; o[nt][3] *= a1;
        }

        uint32_t pa[4][4];
        #pragma unroll
        for (int kv = 0; kv < 4; kv++) {
            pa[kv][0] = packh2(s_acc[2 * kv][0],     s_acc[2 * kv][1]);
            pa[kv][1] = packh2(s_acc[2 * kv][2],     s_acc[2 * kv][3]);
            pa[kv][2] = packh2(s_acc[2 * kv + 1][0], s_acc[2 * kv + 1][1]);
            pa[kv][3] = packh2(s_acc[2 * kv + 1][2], s_acc[2 * kv + 1][3]);
        }

        #pragma unroll
        for (int kv = 0; kv < 4; kv++) {
            #pragma unroll
            for (int dt = 0; dt < 4; dt++) {
                int row = kv * 16 + rV;
                uint32_t vd = vb + (uint32_t)(row * 128 +
                              16 * ((dt * 2 + hV) ^ (row & 7)));
                uint32_t b0, b1, b2, b3;
                LDMATRIX_X4_T(b0, b1, b2, b3, vd);
                MMA_F16(o[dt * 2],     pa[kv][0], pa[kv][1], pa[kv][2], pa[kv][3], b0, b1);
                MMA_F16(o[dt * 2 + 1], pa[kv][0], pa[kv][1], pa[kv][2], pa[kv][3], b2, b3);
            }
        }
    }

    float inv0 = 1.f / l0, inv1 = 1.f / l1;
    size_t row0 = (size_t)b * TSEQ + qt * 64 + w * 16 + r0loc;
    __half* y0 = y + row0 * CDIM + h * DHEAD + cq * 2;
    __half* y1 = y0 + 8 * CDIM;
    #pragma unroll
    for (int nt = 0; nt < 8; nt++) {
        *(__half2*)(y0 + nt * 8) = __floats2half2_rn(o[nt][0] * inv0, o[nt][1] * inv0);
        *(__half2*)(y1 + nt * 8) = __floats2half2_rn(o[nt][2] * inv1, o[nt][3] * inv1);
    }
    #undef LOADKV
    #undef SWOFF
}

// ---------------- launch ----------------
extern "C" void kernel_launch(void* const* d_in, const int* in_sizes, int n_in,
                              void* d_out, int out_size)
{
    const int*   idx    = (const int*)  d_in[0];
    const float* wte    = (const float*)d_in[1];
    const float* wpe    = (const float*)d_in[2];
    const float* ln1_w  = (const float*)d_in[3];
    const float* ln1_b  = (const float*)d_in[4];
    const float* w_qkv  = (const float*)d_in[5];
    const float* b_qkv  = (const float*)d_in[6];
    const float* w_ao   = (const float*)d_in[7];
    const float* b_ao   = (const float*)d_in[8];
    const float* ln2_w  = (const float*)d_in[9];
    const float* ln2_b  = (const float*)d_in[10];
    const float* w_fc   = (const float*)d_in[11];
    const float* b_fc   = (const float*)d_in[12];
    const float* w_fp   = (const float*)d_in[13];
    const float* b_fp   = (const float*)d_in[14];
    const float* lnf_w  = (const float*)d_in[15];
    const float* lnf_b  = (const float*)d_in[16];
    const float* w_head = (const float*)d_in[17];
    float* out = (float*)d_out;

    float *x;
    __half *qkvh, *hh, *yh, *fch, *wqkvT, *waoT, *wfcT, *wfpT;
    cudaGetSymbolAddress((void**)&x,    g_x);
    cudaGetSymbolAddress((void**)&qkvh, g_qkv);
    cudaGetSymbolAddress((void**)&hh,   g_h);
    cudaGetSymbolAddress((void**)&yh,   g_y);
    cudaGetSymbolAddress((void**)&fch,  g_fc);
    cudaGetSymbolAddress((void**)&wqkvT, g_wqkvT);
    cudaGetSymbolAddress((void**)&waoT,  g_waoT);
    cudaGetSymbolAddress((void**)&wfcT,  g_wfcT);
    cudaGetSymbolAddress((void**)&wfpT,  g_wfpT);

    cudaFuncSetAttribute(attn_mma, cudaFuncAttributeMaxDynamicSharedMemorySize, AT_SMEM);
    cudaFuncSetAttribute(hgemm<1,2>, cudaFuncAttributeMaxDynamicSharedMemorySize, HG_SMEM2);
    cudaFuncSetAttribute(hgemm<2,4>, cudaFuncAttributeMaxDynamicSharedMemorySize, HG_SMEM4);
    cudaFuncSetAttribute(hgemm<3,4>, cudaFuncAttributeMaxDynamicSharedMemorySize, HG_SMEM4);

    transpose_kernel<<<dim3(C3 / 64, CDIM / 64, LAYERS), 256>>>(w_qkv, wqkvT, CDIM, C3);
    transpose_kernel<<<dim3(CDIM / 64, CDIM / 64, LAYERS), 256>>>(w_ao, waoT, CDIM, CDIM);
    transpose_kernel<<<dim3(C4 / 64, CDIM / 64, LAYERS), 256>>>(w_fc, wfcT, CDIM, C4);
    transpose_kernel<<<dim3(CDIM / 64, C4 / 64, LAYERS), 256>>>(w_fp, wfpT, C4, CDIM);

    embed_kernel<<<(MROWS * CDIM) / 256, 256>>>(idx, wte, wpe, x);

    for (int l = 0; l < LAYERS; l++) {
        ln_kernel<<<MROWS, 256>>>(x, ln1_w + l * CDIM, ln1_b + l * CDIM, hh);
        hgemm<3,4><<<dim3(C3 / 128, MROWS / 128), 128, HG_SMEM4>>>(
            hh, wqkvT + (size_t)l * C3 * CDIM, b_qkv + l * C3, nullptr, qkvh,
            MROWS, C3, CDIM);
        attn_mma<<<dim3(TSEQ / 64, BATCH * HEADS), 128, AT_SMEM>>>(qkvh, yh);
        hgemm<1,2><<<dim3(CDIM / 128, MROWS / 64), 128, HG_SMEM2>>>(
            yh, waoT + (size_t)l * CDIM * CDIM, b_ao + l * CDIM, x, x,
            MROWS, CDIM, CDIM);
        ln_kernel<<<MROWS, 256>>>(x, ln2_w + l * CDIM, ln2_b + l * CDIM, hh);
        hgemm<2,4><<<dim3(C4 / 128, MROWS / 128), 128, HG_SMEM4>>>(
            hh, wfcT + (size_t)l * C4 * CDIM, b_fc + l * C4, nullptr, fch,
            MROWS, C4, CDIM);
        hgemm<1,2><<<dim3(CDIM / 128, MROWS / 64), 128, HG_SMEM2>>>(
            fch, wfpT + (size_t)l * CDIM * C4, b_fp + l * CDIM, x, x,
            MROWS, CDIM, C4);
    }

    head_kernel<<<MROWS, 256>>>(x, lnf_w, lnf_b, w_head, out);
}